// round 15
// baseline (speedup 1.0000x reference)
#include <cuda_runtime.h>

// ---------------- problem constants ----------------
#define TDIM   2048
#define BDIM   16384
#define NTS    18431            // TDIM + BDIM - 1
#define MQ     24               // seasonality period == HORIZON
#define XOUT_N (BDIM * TDIM)    // 33554432
#define DEN_N  (BDIM * 48)      // 786432

// ---------------- fused scan+xout config ----------------
#define W_UP   1440             // warm-up steps (60 seasonal cycles)
#define WMACRO (W_UP / MQ)      // 60
#define CH_S   19               // output steps per chunk
#define WPB    7                // scan warps (=chunks) per block
#define K_BT   1024             // threads per block (32 warps; 25 help writes)
#define K_NB   139              // ceil(18431/133); 139 <= 148 SMs -> one wave
#define NCHUNK 1024             // logical chunk-index space
#define BSPAN  (WPB * CH_S)     // 133 scan outputs per block
#define SLICE  (W_UP + BSPAN)   // 1573 ts floats used
#define TSBUF  2080             // >= SLICE+32 pad, >= 2048 (prefix reuse)

#define DB     ((DEN_N + 255) / 256)     // 3072 denorm blocks

// ---------------- device scratch (no allocs allowed) ----------------
__device__ float g_l [NTS];
__device__ float g_s [NTS];
__device__ float g_lstart[NCHUNK];
__device__ float g_lend  [NCHUNK];
__device__ float g_c     [NCHUNK];
__device__ unsigned g_cnt;                    // zero-init; reset each launch

__device__ __forceinline__ float frcp(float x) {
    float r;
    asm("rcp.approx.ftz.f32 %0, %1;" : "=f"(r) : "f"(x));
    return r;
}

// ============ K1: fused scan + prefix + x_out ============
// Warps 0..6 run the lane-per-slot ES scan (R7 numerics, bitwise): one warp =
// one 19-step chunk warm-started 1440 steps back, lane j owns seasonal slot j,
// level chain solved per 24-step macro by a Kogge-Stone affine scan.
// The LAST block to finish runs the 1024-entry prefix product. Then ALL 32
// warps of every block write the block's x_out parallelogram directly from
// smem (x_out[b, t-b] = xn[t] for this block's t range) -- no second pass
// over xn, no g_xn array at all.
__global__ __launch_bounds__(K_BT) void k_scan(
    float* __restrict__ out,
    const float* __restrict__ x,
    const float* __restrict__ alpha_p, const float* __restrict__ gamma_p,
    const float* __restrict__ inits,   const float* __restrict__ level_p)
{
    __shared__ float sm_ts[TSBUF];
    __shared__ float sm_xn[BSPAN + 32];
    __shared__ float sm_l [BSPAN + 32];
    __shared__ float sm_s [BSPAN + 32];
    __shared__ unsigned s_pos;

    const int tid        = threadIdx.x;
    const int wid        = tid >> 5;
    const int lane       = tid & 31;
    const int blk_t0     = blockIdx.x * BSPAN;
    const int slice_base = blk_t0 - W_UP;

    // stage ts slice: ts[u] = (u < T) ? x[0,u,0] : x[u-T+1, T-1, 0]
    for (int idx = tid; idx < SLICE + 32; idx += K_BT) {
        int u = slice_base + idx;
        float v = 1.0f;
        if (u >= 0 && u < NTS)
            v = (u < TDIM) ? x[u] : x[(u - (TDIM - 1)) * TDIM + (TDIM - 1)];
        sm_ts[idx] = v;
    }
    __syncthreads();

    if (wid < WPB) {
        const float a  = *alpha_p;
        const float g  = *gamma_p;
        const float ka = 1.0f - a;
        const float kg = 1.0f - g;
        const float ka2 = ka * ka, ka4 = ka2 * ka2, ka8 = ka4 * ka4, ka16 = ka8 * ka8;

        const int chunk = blockIdx.x * WPB + wid;      // <= 972 < NCHUNK
        const int t0    = chunk * CH_S;
        const int u0    = t0 - W_UP;
        const int base  = wid * CH_S;    // sm_ts index of this warp's u0

        // per-lane constant ka^(lane+1)
        float kaPow = ka;
        for (int i = 0; i < lane; i++) kaPow *= ka;

        // lane j owns slot j: q = inits[(j + t0) % 24]
        float q  = inits[(lane + t0) % MQ];
        float iq = frcp(q);
        float l  = *level_p;

        int kk = 0;
        // clamped prefix (chunks with t0 < W_UP): skip whole macros; one
        // partial macro where lanes j < rem use identity affines.
        if (u0 < 0) {
            int m   = (-u0) / MQ;
            int rem = (-u0) % MQ;
            kk = m;
            if (rem > 0) {
                int off = base + kk * MQ;
                float y = sm_ts[off + lane];
                float r = y * iq;
                bool act = (lane >= rem);
                float Av = act ? ka      : 1.0f;
                float Bv = act ? a * r   : 0.0f;
#pragma unroll
                for (int s = 1; s < MQ; s <<= 1) {
                    float Bp = __shfl_up_sync(0xffffffffu, Bv, s);
                    float Ap = __shfl_up_sync(0xffffffffu, Av, s);
                    if (lane >= s) { Bv = fmaf(Av, Bp, Bv); Av *= Ap; }
                }
                float ll = fmaf(Av, l, Bv);
                if (act) {
                    float il = frcp(ll);
                    float sn = fmaf(kg, q, (g * y) * il);
                    q  = sn;
                    iq = frcp(sn);
                }
                l = __shfl_sync(0xffffffffu, ll, MQ - 1);
                kk++;
            }
        }

        // clean warm loop
        for (; kk < WMACRO; kk++) {
            float y = sm_ts[base + kk * MQ + lane];
            float r = y * iq;
            float B = a * r;
            float Bp;
            Bp = __shfl_up_sync(0xffffffffu, B, 1);  if (lane >= 1)  B = fmaf(ka,   Bp, B);
            Bp = __shfl_up_sync(0xffffffffu, B, 2);  if (lane >= 2)  B = fmaf(ka2,  Bp, B);
            Bp = __shfl_up_sync(0xffffffffu, B, 4);  if (lane >= 4)  B = fmaf(ka4,  Bp, B);
            Bp = __shfl_up_sync(0xffffffffu, B, 8);  if (lane >= 8)  B = fmaf(ka8,  Bp, B);
            Bp = __shfl_up_sync(0xffffffffu, B, 16); if (lane >= 16) B = fmaf(ka16, Bp, B);
            float ll = fmaf(kaPow, l, B);
            float il = frcp(ll);
            float sn = fmaf(kg, q, (g * y) * il);
            q  = sn;
            iq = frcp(sn);
            l  = __shfl_sync(0xffffffffu, ll, MQ - 1);
        }

        if (lane == 0) g_lstart[chunk] = l;    // level entering t0

        // output phase: 19 steps (lanes 0..18 produce results)
        {
            float y = sm_ts[base + WMACRO * MQ + lane];
            float r = y * iq;
            float B = a * r;
            float Bp;
            Bp = __shfl_up_sync(0xffffffffu, B, 1);  if (lane >= 1)  B = fmaf(ka,   Bp, B);
            Bp = __shfl_up_sync(0xffffffffu, B, 2);  if (lane >= 2)  B = fmaf(ka2,  Bp, B);
            Bp = __shfl_up_sync(0xffffffffu, B, 4);  if (lane >= 4)  B = fmaf(ka4,  Bp, B);
            Bp = __shfl_up_sync(0xffffffffu, B, 8);  if (lane >= 8)  B = fmaf(ka8,  Bp, B);
            Bp = __shfl_up_sync(0xffffffffu, B, 16); if (lane >= 16) B = fmaf(ka16, Bp, B);
            float ll = fmaf(kaPow, l, B);
            float il = frcp(ll);
            float sn = fmaf(kg, q, (g * y) * il);
            if (lane < CH_S) {
                int oo = base + lane;
                sm_xn[oo] = r * il;
                sm_l [oo] = ll;
                sm_s [oo] = sn;
            }
            float le = __shfl_sync(0xffffffffu, ll, CH_S - 1);
            if (lane == 0) g_lend[chunk] = le;   // level entering t0 + 19
        }
    }
    __syncthreads();

    const int span = (NTS - blk_t0 < BSPAN) ? (NTS - blk_t0) : BSPAN;
    // persist l/s for the denorm kernel
    for (int idx = tid; idx < span; idx += K_BT) {
        int t = blk_t0 + idx;
        g_l[t] = sm_l[idx];
        g_s[t] = sm_s[idx];
    }

    // ---- last-block prefix product (needs all lstart/lend visible) ----
    __threadfence();
    __syncthreads();
    if (tid == 0) s_pos = atomicAdd(&g_cnt, 1u);
    __syncthreads();
    if (s_pos == K_NB - 1) {
        // 1024 threads, one element each: the ORIGINAL k_prefix sequence
        float* c = sm_ts;                  // sm_ts free now (>= 1024 floats)
        int k = tid;
        float ratio = 1.0f;
        if (k > 0 && k * CH_S < NTS) ratio = g_lstart[k] / g_lend[k - 1];
        c[k] = ratio;
        __syncthreads();
        for (int o = 1; o < NCHUNK; o <<= 1) {
            float v = (k >= o) ? c[k - o] : 1.0f;
            __syncthreads();
            c[k] *= v;
            __syncthreads();
        }
        g_c[k] = c[k];
        if (tid == 0) g_cnt = 0;           // deterministic reset for replay
    }

    // ---- x_out parallelogram: x_out[b, t-b] = sm_xn[t - blk_t0] ----
    // rows b with a nonempty column range [c0, c1); per row <= 133 consecutive
    // floats -> coalesced 128B scalar stores straight from smem.
    {
        const int tmax = blk_t0 + span;
        int blo = blk_t0 - (TDIM - 1); if (blo < 0) blo = 0;
        int bhi = tmax - 1;            if (bhi > BDIM - 1) bhi = BDIM - 1;
        const int w32 = tid >> 5;
        for (int b = blo + w32; b <= bhi; b += 32) {
            int c0 = blk_t0 - b; if (c0 < 0) c0 = 0;
            int c1 = tmax - b;   if (c1 > TDIM) c1 = TDIM;
            float* orow = out + b * TDIM;
            int off = b - blk_t0;          // sm_xn index = off + c (>= 0)
            for (int c = c0 + lane; c < c1; c += 32)
                __stcs(&orow[c], sm_xn[off + c]);
        }
    }
}

// ============ K2: denorm (correction applied at read time) ============
__global__ __launch_bounds__(256) void k_den(float* __restrict__ out) {
    int i = blockIdx.x * 256 + threadIdx.x;
    if (i < DEN_N) {
        int b = i / 48;
        int r = i - b * 48;
        int h = r >> 1;
        float v;
        if (r & 1) {
            int t = (TDIM - MQ) + b + h;
            v = g_s[t] * g_c[t / CH_S];          // s_true = s * c
        } else {
            int t = (TDIM - 1) + b;
            v = g_l[t] / g_c[t / CH_S];          // l_true = l / c
        }
        out[XOUT_N + i] = v;
    }
}

extern "C" void kernel_launch(void* const* d_in, const int* in_sizes, int n_in,
                              void* d_out, int out_size) {
    const float* x     = (const float*)d_in[0];
    const float* alpha = (const float*)d_in[1];
    const float* gamma = (const float*)d_in[2];
    const float* inits = (const float*)d_in[3];
    const float* level = (const float*)d_in[4];
    float* out = (float*)d_out;

    k_scan<<<K_NB, K_BT>>>(out, x, alpha, gamma, inits, level);
    if (out_size >= XOUT_N + DEN_N)
        k_den<<<DB, 256>>>(out);
}